// round 1
// baseline (speedup 1.0000x reference)
#include <cuda_runtime.h>
#include <cuda_bf16.h>

#define TILE 256

// Global scratch accumulator (allocation-free rule: __device__ global).
__device__ double g_acc;

__global__ void dl_init_kernel() {
    g_acc = 0.0;
}

__global__ void dl_tile_kernel(const float* __restrict__ p,
                               const float* __restrict__ z_spacing,
                               const float* __restrict__ nth_slice,
                               int n) {
    __shared__ float pj[TILE];
    __shared__ double warp_sums[TILE / 32];

    // Decode lower-triangular tile pair (bi, bj), bj <= bi, from linear block id.
    int t = blockIdx.x;
    int bi = (int)((sqrtf(8.0f * (float)t + 1.0f) - 1.0f) * 0.5f);
    while ((bi + 1) * (bi + 2) / 2 <= t) bi++;
    while (bi * (bi + 1) / 2 > t) bi--;
    int bj = t - bi * (bi + 1) / 2;

    const float step = 1.0f * z_spacing[0] * nth_slice[0];

    const int gi  = bi * TILE + (int)threadIdx.x;
    const int gj0 = bj * TILE;

    // Load j-tile into shared memory (broadcast reads in the inner loop).
    int gj_load = gj0 + (int)threadIdx.x;
    pj[threadIdx.x] = (gj_load < n) ? p[gj_load] : 0.0f;
    const bool i_valid = (gi < n);
    const float pi = i_valid ? p[gi] : 0.0f;
    __syncthreads();

    const int jmax = min(TILE, n - gj0);

    float acc = 0.0f;
    if (i_valid) {
        if (bi != bj) {
            // Off-diagonal tile: every (i, j) has i - j >= TILE > 0. Branch-free.
            #pragma unroll 8
            for (int jj = 0; jj < TILE; ++jj) {
                if (jj >= jmax) break;
                int delta = gi - (gj0 + jj);
                float s = (float)delta * step;
                float d = pi - pj[jj];
                // Exact fp32 op sequence of the reference:
                if (d >= 0.0f) d = d - 0.2f * s;
                if (d >= 0.0f) d = fmaxf(d - 0.8f * s, 0.0f);
                acc += fabsf(d);
            }
        } else {
            // Diagonal tile: only j < i contributes (j == i contributes 0).
            #pragma unroll 4
            for (int jj = 0; jj < TILE; ++jj) {
                if (jj >= jmax) break;
                int delta = (int)threadIdx.x - jj;
                if (delta > 0) {
                    float s = (float)delta * step;
                    float d = pi - pj[jj];
                    if (d >= 0.0f) d = d - 0.2f * s;
                    if (d >= 0.0f) d = fmaxf(d - 0.8f * s, 0.0f);
                    acc += fabsf(d);
                }
            }
        }
    }

    // Block reduction in double, then one atomicAdd per block.
    double dacc = (double)acc;
    #pragma unroll
    for (int off = 16; off > 0; off >>= 1)
        dacc += __shfl_down_sync(0xffffffff, dacc, off);
    if ((threadIdx.x & 31) == 0) warp_sums[threadIdx.x >> 5] = dacc;
    __syncthreads();
    if (threadIdx.x < (TILE / 32)) {
        double v = warp_sums[threadIdx.x];
        #pragma unroll
        for (int off = (TILE / 64); off > 0; off >>= 1)
            v += __shfl_down_sync(0xff, v, off);
        if (threadIdx.x == 0) atomicAdd(&g_acc, v);
    }
}

__global__ void dl_finalize_kernel(float* __restrict__ out, int n) {
    double nn = (double)n * (double)n;
    out[0] = (float)(g_acc / nn);
}

extern "C" void kernel_launch(void* const* d_in, const int* in_sizes, int n_in,
                              void* d_out, int out_size) {
    const float* p   = (const float*)d_in[0];
    const float* z   = (const float*)d_in[1];
    const float* nth = (const float*)d_in[2];
    float* out = (float*)d_out;
    int n = in_sizes[0];

    int ntiles = (n + TILE - 1) / TILE;
    int nblocks = ntiles * (ntiles + 1) / 2;

    dl_init_kernel<<<1, 1>>>();
    dl_tile_kernel<<<nblocks, TILE>>>(p, z, nth, n);
    dl_finalize_kernel<<<1, 1>>>(out, n);
}

// round 2
// speedup vs baseline: 1.5458x; 1.5458x over previous
#include <cuda_runtime.h>
#include <cuda_bf16.h>

#define TILE 256
#define MAXB 4096

// Scratch (allocation-free rule: __device__ globals).
__device__ double        g_partials[MAXB];
__device__ unsigned int  g_ticket = 0;

__global__ void __launch_bounds__(TILE)
dl_fused_kernel(const float* __restrict__ p,
                const float* __restrict__ z_spacing,
                const float* __restrict__ nth_slice,
                float* __restrict__ out,
                int n, int nblocks) {
    __shared__ float4 qt[TILE];
    __shared__ double wsum[TILE / 32];
    __shared__ bool   is_last;

    const int tid = threadIdx.x;

    // Decode lower-triangular tile pair (bi, bj), bj <= bi, from linear block id.
    int t = blockIdx.x;
    int bi = (int)((sqrtf(8.0f * (float)t + 1.0f) - 1.0f) * 0.5f);
    while ((bi + 1) * (bi + 2) / 2 <= t) bi++;
    while (bi * (bi + 1) / 2 > t) bi--;
    const int bj = t - bi * (bi + 1) / 2;

    const float step = z_spacing[0] * nth_slice[0];   // STEP == 1.0
    const float c02  = 0.2f * step;

    const int gi  = bi * TILE + tid;
    const int gj0 = bj * TILE;
    const int gj  = gj0 + tid;

    // Per-j precompute: q.x = pj - 0.2*step*j ; q.y = step*j - pj ; q.z = pj
    {
        float pv = (gj < n) ? p[gj] : 0.0f;
        float jf = (float)gj;
        qt[tid] = make_float4(pv - c02 * jf, step * jf - pv, pv, 0.0f);
    }

    const bool  i_valid = (gi < n);
    const float pi = i_valid ? p[gi] : 0.0f;
    // Per-i precompute: t1 = P1 + q.x ; t2 = P2 + q.y
    const float gif = (float)gi;
    const float P1  = c02  * gif - pi;
    const float P2  = pi - step * gif;

    __syncthreads();

    float acc = 0.0f;
    if (i_valid) {
        if (bi != bj) {
            // Off-diagonal tile: all pairs valid (i - j >= TILE). Branch-free body.
            const int jcnt = min(TILE, n - gj0);
            #pragma unroll 16
            for (int jj = 0; jj < jcnt; ++jj) {
                float4 q = qt[jj];
                float t1 = P1 + q.x;           // 0.2*s - d
                float t2 = P2 + q.y;           // d - s
                float m  = fmaxf(fmaxf(t1, t2), 0.0f);
                float r  = (q.z > pi) ? (q.z - pi) : m;  // d<0 branch of reference
                acc += r;
            }
        } else {
            // Diagonal tile: j <= i only (j == i contributes exactly 0 in this form).
            #pragma unroll 4
            for (int jj = 0; jj <= tid; ++jj) {
                float4 q = qt[jj];
                float t1 = P1 + q.x;
                float t2 = P2 + q.y;
                float m  = fmaxf(fmaxf(t1, t2), 0.0f);
                float r  = (q.z > pi) ? (q.z - pi) : m;
                acc += r;
            }
        }
    }

    // Block reduction in double.
    double v = (double)acc;
    #pragma unroll
    for (int off = 16; off > 0; off >>= 1)
        v += __shfl_down_sync(0xffffffffu, v, off);
    if ((tid & 31) == 0) wsum[tid >> 5] = v;
    __syncthreads();
    if (tid < 32) {
        v = (tid < (TILE / 32)) ? wsum[tid] : 0.0;
        #pragma unroll
        for (int off = 4; off > 0; off >>= 1)
            v += __shfl_down_sync(0xffffffffu, v, off);
        if (tid == 0) {
            g_partials[blockIdx.x] = v;
            __threadfence();
            unsigned int ticket = atomicAdd(&g_ticket, 1u);
            is_last = (ticket == (unsigned int)(nblocks - 1));
        }
    }
    __syncthreads();

    // Last block: reduce all partials, write output, reset ticket.
    if (is_last) {
        __threadfence();
        double s = 0.0;
        for (int i = tid; i < nblocks; i += TILE)
            s += g_partials[i];
        #pragma unroll
        for (int off = 16; off > 0; off >>= 1)
            s += __shfl_down_sync(0xffffffffu, s, off);
        if ((tid & 31) == 0) wsum[tid >> 5] = s;
        __syncthreads();
        if (tid == 0) {
            double tot = 0.0;
            #pragma unroll
            for (int w = 0; w < TILE / 32; ++w) tot += wsum[w];
            double nn = (double)n * (double)n;
            out[0] = (float)(tot / nn);
            g_ticket = 0;   // reset for next graph replay
        }
    }
}

extern "C" void kernel_launch(void* const* d_in, const int* in_sizes, int n_in,
                              void* d_out, int out_size) {
    const float* p   = (const float*)d_in[0];
    const float* z   = (const float*)d_in[1];
    const float* nth = (const float*)d_in[2];
    float* out = (float*)d_out;
    int n = in_sizes[0];

    int ntiles  = (n + TILE - 1) / TILE;
    int nblocks = ntiles * (ntiles + 1) / 2;
    if (nblocks > MAXB) nblocks = MAXB;  // safety; n=8192 -> 528

    dl_fused_kernel<<<nblocks, TILE>>>(p, z, nth, out, n, nblocks);
}